// round 1
// baseline (speedup 1.0000x reference)
#include <cuda_runtime.h>
#include <math.h>

// Problem constants: B=16, L=S=1024, H=8, E=64, d=512
#define LSEQ 1024
#define LF   513
#define NBH  128            // B*H
#define ATTN_SMEM (3*64*66*sizeof(float2) + 16*64*sizeof(float))

// -------- scratch (device globals; no allocation allowed) --------
__device__ float  g_y [16777216];            // conv output [B*L][1024]  (67MB)
__device__ float  g_Wt[1536 * 1024];         // transposed weights [kk][o] (6MB)
__device__ float2 g_qf[(size_t)NBH * LF * 64];
__device__ float2 g_kf[(size_t)NBH * LF * 64];
__device__ float2 g_vf[(size_t)NBH * LF * 64];
__device__ float2 g_of[(size_t)NBH * LF * 64];

// =============== W transpose: W[o][i][t] -> Wt[t*512+i][o] ===============
__global__ void k_transpose_w(const float* __restrict__ W) {
    int idx = blockIdx.x * blockDim.x + threadIdx.x;
    if (idx >= 1024 * 512 * 3) return;
    int o = idx / 1536;
    int r = idx - o * 1536;
    int i = r / 3;
    int t = r - i * 3;
    g_Wt[(t * 512 + i) * 1024 + o] = W[idx];
}

// =============== Conv1d as im2col GEMM: y[m][n] = sum_kk A[m][kk]*Wt[kk][n] + b[n] ===============
// M=16384, N=1024, K=1536. 128x128 tile, 8x8 per thread, 256 threads.
__global__ __launch_bounds__(256) void k_conv_gemm(const float* __restrict__ x,
                                                   const float* __restrict__ bias) {
    __shared__ float As[8][128];   // [k][m]
    __shared__ float Bs[8][128];   // [k][n]
    const int m0 = blockIdx.y * 128;
    const int n0 = blockIdx.x * 128;
    const int tid = threadIdx.x;
    const int tx = tid & 15, ty = tid >> 4;
    const int a_m = tid >> 1, a_k4 = (tid & 1) * 4;
    const int b_k = tid >> 5, b_n4 = (tid & 31) * 4;

    float acc[8][8];
#pragma unroll
    for (int i = 0; i < 8; i++)
#pragma unroll
        for (int j = 0; j < 8; j++) acc[i][j] = 0.f;

    const int m_ld = m0 + a_m;
    const int bb = m_ld >> 10, l = m_ld & 1023;

    for (int kk = 0; kk < 1536; kk += 8) {
        const int t  = kk >> 9;                 // 8-chunks never straddle a tap boundary
        const int i0 = (kk & 511) + a_k4;
        const int lp = l + t - 1;
        float4 av = make_float4(0.f, 0.f, 0.f, 0.f);
        if (lp >= 0 && lp < 1024)
            av = *(const float4*)(x + ((size_t)bb * 1024 + lp) * 512 + i0);
        As[a_k4 + 0][a_m] = av.x;
        As[a_k4 + 1][a_m] = av.y;
        As[a_k4 + 2][a_m] = av.z;
        As[a_k4 + 3][a_m] = av.w;
        *(float4*)&Bs[b_k][b_n4] =
            *(const float4*)(g_Wt + (size_t)(kk + b_k) * 1024 + n0 + b_n4);
        __syncthreads();
#pragma unroll
        for (int k = 0; k < 8; k++) {
            float a[8], b[8];
#pragma unroll
            for (int i = 0; i < 8; i++) a[i] = As[k][ty * 8 + i];
#pragma unroll
            for (int j = 0; j < 8; j++) b[j] = Bs[k][tx * 8 + j];
#pragma unroll
            for (int i = 0; i < 8; i++)
#pragma unroll
                for (int j = 0; j < 8; j++) acc[i][j] = fmaf(a[i], b[j], acc[i][j]);
        }
        __syncthreads();
    }
#pragma unroll
    for (int i = 0; i < 8; i++) {
        float* yr = g_y + (size_t)(m0 + ty * 8 + i) * 1024 + n0 + tx * 8;
#pragma unroll
        for (int j = 0; j < 8; j++) yr[j] = acc[i][j] + bias[n0 + tx * 8 + j];
    }
}

// =============== 1024-pt Stockham radix-2 FFT in shared memory ===============
// 256 threads, 2 butterflies/thread/stage. Result ends in s0 (natural order).
__device__ __forceinline__ void fft1024_sm(float2* s0, float2* s1, int tid, float sign) {
    float2* src = s0;
    float2* dst = s1;
    int n = 1024;
    int logstr = 0;
#pragma unroll
    for (int st = 0; st < 10; st++) {
        const int m = n >> 1;
        const int str = 1 << logstr;
#pragma unroll
        for (int r = 0; r < 2; r++) {
            const int i = tid + r * 256;
            const int p = i >> logstr;
            const int q = i & (str - 1);
            const float2 a = src[q + str * p];
            const float2 b = src[q + str * (p + m)];
            const float2 su = make_float2(a.x + b.x, a.y + b.y);
            const float2 di = make_float2(a.x - b.x, a.y - b.y);
            const float ang = sign * 2.0f * (float)p / (float)n;  // units of pi
            float sw, cw;
            sincospif(ang, &sw, &cw);
            dst[q + str * (2 * p)]     = su;
            dst[q + str * (2 * p + 1)] = make_float2(di.x * cw - di.y * sw,
                                                     di.x * sw + di.y * cw);
        }
        __syncthreads();
        float2* tp = src; src = dst; dst = tp;
        n >>= 1;
        logstr++;
    }
}

// =============== forward rFFT (ortho): one (b, channel) sequence per block ===============
// mode 0: q2 = GLU(conv output) -> g_qf ; mode 1: k -> g_kf ; mode 2: v -> g_vf
__global__ __launch_bounds__(256) void k_fft_fwd(const float* __restrict__ in, int mode) {
    __shared__ float2 s0[1024];
    __shared__ float2 s1[1024];
    const int seq = blockIdx.x;              // b*512 + c,  c = h*64+e
    const int b = seq >> 9, c = seq & 511;
    const int tid = threadIdx.x;
    for (int l = tid; l < 1024; l += 256) {
        float v;
        if (mode == 0) {
            const float* yr = g_y + ((size_t)(b * 1024 + l)) * 1024;
            const float a = yr[c];
            const float g = yr[c + 512];
            v = a * (1.0f / (1.0f + __expf(-g)));   // GLU
        } else {
            v = in[((size_t)(b * 1024 + l)) * 512 + c];
        }
        s0[l] = make_float2(v, 0.f);
    }
    __syncthreads();
    fft1024_sm(s0, s1, tid, -1.0f);
    float2* outp = (mode == 0) ? g_qf : (mode == 1 ? g_kf : g_vf);
    const int bh = b * 8 + (c >> 6), e = c & 63;
    float2* o = outp + (size_t)bh * LF * 64 + e;
    const float sc = 1.0f / 32.0f;           // ortho: 1/sqrt(1024)
    for (int xx = tid; xx < LF; xx += 256) {
        const float2 t = s0[xx];
        o[(size_t)xx * 64] = make_float2(t.x * sc, t.y * sc);
    }
}

// =============== fused frequency-domain flash attention ===============
// Per (bh, x-tile of 64): S = Qf·conj(Kf)^T/8, weight w=1+sigmoid(|s|),
// O = (S.*w) @ Vf, denom = rowsum(|s|*w), O /= max(denom,1e-12).
__global__ __launch_bounds__(256) void k_attn() {
    extern __shared__ float2 sm[];
    float2 (*Qs)[66] = (float2(*)[66])sm;                 // [e][x]
    float2 (*KP)[66] = (float2(*)[66])(sm + 64 * 66);     // K:[e][y] then P:[y][x]
    float2 (*Vs)[66] = (float2(*)[66])(sm + 2 * 64 * 66); // [y][e]
    float* dpart = (float*)(sm + 3 * 64 * 66);            // [16][64]

    const int bh = blockIdx.x;
    const int x0 = blockIdx.y * 64;
    const int tid = threadIdx.x;
    const int tx = tid & 15, ty = tid >> 4;

    const float2* Qg = g_qf + (size_t)bh * LF * 64;
    const float2* Kg = g_kf + (size_t)bh * LF * 64;
    const float2* Vg = g_vf + (size_t)bh * LF * 64;

    // load Q tile (zero-padded past LF)
#pragma unroll
    for (int r = 0; r < 16; r++) {
        const int idx = tid + r * 256;
        const int xl = idx >> 6, e = idx & 63;
        float2 v = make_float2(0.f, 0.f);
        if (x0 + xl < LF) v = Qg[(size_t)(x0 + xl) * 64 + e];
        Qs[e][xl] = v;
    }

    float oar[4][4], oai[4][4];
#pragma unroll
    for (int i = 0; i < 4; i++)
#pragma unroll
        for (int j = 0; j < 4; j++) { oar[i][j] = 0.f; oai[i][j] = 0.f; }
    float dloc[4] = {0.f, 0.f, 0.f, 0.f};
    __syncthreads();

    for (int y0 = 0; y0 < LF; y0 += 64) {
        // load K,V tiles (zero-padded: zeros contribute nothing to P or denom)
#pragma unroll
        for (int r = 0; r < 16; r++) {
            const int idx = tid + r * 256;
            const int yl = idx >> 6, e = idx & 63;
            float2 kv = make_float2(0.f, 0.f), vv = make_float2(0.f, 0.f);
            if (y0 + yl < LF) {
                kv = Kg[(size_t)(y0 + yl) * 64 + e];
                vv = Vg[(size_t)(y0 + yl) * 64 + e];
            }
            KP[e][yl] = kv;
            Vs[yl][e] = vv;
        }
        __syncthreads();

        float sr[4][4], si[4][4];
#pragma unroll
        for (int i = 0; i < 4; i++)
#pragma unroll
            for (int j = 0; j < 4; j++) { sr[i][j] = 0.f; si[i][j] = 0.f; }

#pragma unroll 8
        for (int e = 0; e < 64; e++) {
            float2 qa[4], kb[4];
#pragma unroll
            for (int i = 0; i < 4; i++) qa[i] = Qs[e][tx * 4 + i];
#pragma unroll
            for (int j = 0; j < 4; j++) kb[j] = KP[e][ty * 4 + j];
#pragma unroll
            for (int i = 0; i < 4; i++)
#pragma unroll
                for (int j = 0; j < 4; j++) {
                    // s += q * conj(k)
                    sr[i][j] = fmaf(qa[i].x, kb[j].x, fmaf(qa[i].y, kb[j].y, sr[i][j]));
                    si[i][j] = fmaf(qa[i].y, kb[j].x, fmaf(-qa[i].x, kb[j].y, si[i][j]));
                }
        }
        __syncthreads();   // everyone done reading K before P overwrites it

#pragma unroll
        for (int i = 0; i < 4; i++)
#pragma unroll
            for (int j = 0; j < 4; j++) {
                const float re = sr[i][j] * 0.125f;   // /sqrt(E)
                const float im = si[i][j] * 0.125f;
                const float mag = __fsqrt_rn(re * re + im * im);
                const float w = 1.0f + 1.0f / (1.0f + __expf(-mag));
                dloc[i] += mag * w;
                KP[ty * 4 + j][tx * 4 + i] = make_float2(re * w, im * w);
            }
        __syncthreads();

#pragma unroll 8
        for (int y = 0; y < 64; y++) {
            float2 pa[4], vb[4];
#pragma unroll
            for (int i = 0; i < 4; i++) pa[i] = KP[y][tx * 4 + i];
#pragma unroll
            for (int j = 0; j < 4; j++) vb[j] = Vs[y][ty * 4 + j];
#pragma unroll
            for (int i = 0; i < 4; i++)
#pragma unroll
                for (int j = 0; j < 4; j++) {
                    // o += p * v  (plain complex product)
                    oar[i][j] = fmaf(pa[i].x, vb[j].x, fmaf(-pa[i].y, vb[j].y, oar[i][j]));
                    oai[i][j] = fmaf(pa[i].x, vb[j].y, fmaf(pa[i].y, vb[j].x, oai[i][j]));
                }
        }
        __syncthreads();   // before next tile's K/V load
    }

    // deterministic denominator reduction (fixed order, no atomics)
#pragma unroll
    for (int i = 0; i < 4; i++) dpart[ty * 64 + tx * 4 + i] = dloc[i];
    __syncthreads();

    float2* Og = g_of + (size_t)bh * LF * 64;
#pragma unroll
    for (int i = 0; i < 4; i++) {
        const int xl = tx * 4 + i;
        const int xg = x0 + xl;
        if (xg >= LF) continue;
        float dn = 0.f;
#pragma unroll
        for (int t = 0; t < 16; t++) dn += dpart[t * 64 + xl];
        const float inv = 1.0f / fmaxf(dn, 1e-12f);
#pragma unroll
        for (int j = 0; j < 4; j++)
            Og[(size_t)xg * 64 + ty * 4 + j] =
                make_float2(oar[i][j] * inv, oai[i][j] * inv);
    }
}

// =============== inverse: Hermitian extension + iFFT, real part (ortho) ===============
__global__ __launch_bounds__(256) void k_fft_inv(float* __restrict__ out) {
    __shared__ float2 s0[1024];
    __shared__ float2 s1[1024];
    const int seq = blockIdx.x;             // bh*64 + e
    const int bh = seq >> 6, e = seq & 63;
    const float2* ip = g_of + (size_t)bh * LF * 64 + e;
    const int tid = threadIdx.x;
    for (int xx = tid; xx < 1024; xx += 256) {
        float2 v;
        if (xx <= 512) {
            v = ip[(size_t)xx * 64];
        } else {
            const float2 t = ip[(size_t)(1024 - xx) * 64];
            v = make_float2(t.x, -t.y);
        }
        s0[xx] = v;
    }
    __syncthreads();
    fft1024_sm(s0, s1, tid, +1.0f);
    const int b = bh >> 3, h = bh & 7;
    float* op = out + (size_t)b * 1024 * 512 + h * 64 + e;
    const float sc = 1.0f / 32.0f;          // ortho inverse scale
    for (int l = tid; l < 1024; l += 256) op[(size_t)l * 512] = s0[l].x * sc;
}

// ============================ launch ============================
extern "C" void kernel_launch(void* const* d_in, const int* in_sizes, int n_in,
                              void* d_out, int out_size) {
    const float* q    = (const float*)d_in[0];
    const float* k    = (const float*)d_in[1];
    const float* v    = (const float*)d_in[2];
    const float* W    = (const float*)d_in[3];
    const float* bias = (const float*)d_in[4];
    float* out = (float*)d_out;

    cudaFuncSetAttribute(k_attn, cudaFuncAttributeMaxDynamicSharedMemorySize,
                         (int)ATTN_SMEM);

    k_transpose_w<<<(1024 * 512 * 3 + 255) / 256, 256>>>(W);
    k_conv_gemm<<<dim3(8, 128), 256>>>(q, bias);
    k_fft_fwd<<<8192, 256>>>(nullptr, 0);   // q2 (GLU of conv output)
    k_fft_fwd<<<8192, 256>>>(k, 1);
    k_fft_fwd<<<8192, 256>>>(v, 2);
    k_attn<<<dim3(128, 9), 256, ATTN_SMEM>>>();
    k_fft_inv<<<8192, 256>>>(out);
}